// round 3
// baseline (speedup 1.0000x reference)
#include <cuda_runtime.h>
#include <math.h>

#define S 8192
#define D 2048
#define WSTRIDE 4096           // W row stride (2*D)
#define NCTA_REC 128
#define ROWS_PER_CTA 16        // D / NCTA_REC
#define NCHUNK 64
#define CHUNK 128              // S / NCHUNK
#define REC_THREADS 512

typedef unsigned long long ull;

// ---- scratch (no runtime allocation allowed) ----
__device__ float g_hc[(size_t)S * D];        // cummax result
__device__ float g_cp[(size_t)S * D];        // ctx_proj result
__device__ float g_chunkmax[NCHUNK * D];     // cummax phase-B scratch
__device__ int   g_flag[NCTA_REC];           // per-CTA monotonic step counter

#define NEG_INF __int_as_float(0xff800000)

__device__ __forceinline__ ull ffma2(ull a, ull b, ull c) {
    ull d;
    asm("fma.rn.f32x2 %0, %1, %2, %3;" : "=l"(d) : "l"(a), "l"(b), "l"(c));
    return d;
}
__device__ __forceinline__ ull pack2(unsigned int lo, unsigned int hi) {
    ull v;
    asm("mov.b64 %0, {%1, %2};" : "=l"(v) : "r"(lo), "r"(hi));
    return v;
}
__device__ __forceinline__ float2 unpack2(ull v) {
    float2 r;
    asm("mov.b64 {%0, %1}, %2;" : "=f"(r.x), "=f"(r.y) : "l"(v));
    return r;
}

// ============================================================
// flag reset (graph replays must start from zeroed counters)
// ============================================================
__global__ void zero_flags_kernel() {
    int idx = threadIdx.x;
    if (idx < NCTA_REC) g_flag[idx] = 0;
}

// ============================================================
// cummax phase A: per-(chunk, col) max
// ============================================================
__global__ void cummax_chunk_kernel(const float* __restrict__ ce) {
    int col = blockIdx.x * blockDim.x + threadIdx.x;
    int chunk = blockIdx.y;
    const float* p = ce + (size_t)chunk * CHUNK * D + col;
    float m = NEG_INF;
#pragma unroll 8
    for (int r = 0; r < CHUNK; r++) {
        m = fmaxf(m, p[(size_t)r * D]);
    }
    g_chunkmax[chunk * D + col] = m;
}

// ============================================================
// cummax phase B: exclusive prefix-max over chunks, per column
// ============================================================
__global__ void cummax_scan_kernel() {
    int col = blockIdx.x * blockDim.x + threadIdx.x;
    float run = NEG_INF;
    for (int ch = 0; ch < NCHUNK; ch++) {
        float v = g_chunkmax[ch * D + col];
        g_chunkmax[ch * D + col] = run;   // exclusive prefix
        run = fmaxf(run, v);
    }
}

// ============================================================
// cummax phase C: inclusive scan within chunk seeded by prefix
// ============================================================
__global__ void cummax_write_kernel(const float* __restrict__ ce) {
    int col = blockIdx.x * blockDim.x + threadIdx.x;
    int chunk = blockIdx.y;
    float m = g_chunkmax[chunk * D + col];
    const float* p = ce + (size_t)chunk * CHUNK * D + col;
    float*       q = g_hc + (size_t)chunk * CHUNK * D + col;
#pragma unroll 8
    for (int r = 0; r < CHUNK; r++) {
        m = fmaxf(m, p[(size_t)r * D]);
        q[(size_t)r * D] = m;
    }
}

// ============================================================
// GEMM: g_cp[t][i] = sum_j ce[t][j] * W[i][D + j] + b[i]
// ============================================================
#define GT 128
#define GI 128
#define GK 8
#define GPAD 4

__global__ __launch_bounds__(256) void gemm_ctx_kernel(
    const float* __restrict__ A,
    const float* __restrict__ W,
    const float* __restrict__ bias)
{
    __shared__ float As[GK][GT + GPAD];
    __shared__ float Bs[GK][GI + GPAD];

    int tid = threadIdx.x;
    int tx = tid & 15;
    int ty = tid >> 4;
    int i0 = blockIdx.x * GI;
    int t0 = blockIdx.y * GT;

    int lr = tid >> 1;
    int lk = (tid & 1) * 4;

    const float* Ap = A + (size_t)(t0 + lr) * D + lk;
    const float* Bp = W + (size_t)(i0 + lr) * WSTRIDE + D + lk;

    float acc[8][8];
#pragma unroll
    for (int m = 0; m < 8; m++)
#pragma unroll
        for (int n = 0; n < 8; n++) acc[m][n] = 0.0f;

    float4 ra = *(const float4*)Ap;
    float4 rb = *(const float4*)Bp;

    for (int kk = 0; kk < D; kk += GK) {
        As[lk + 0][lr] = ra.x; As[lk + 1][lr] = ra.y;
        As[lk + 2][lr] = ra.z; As[lk + 3][lr] = ra.w;
        Bs[lk + 0][lr] = rb.x; Bs[lk + 1][lr] = rb.y;
        Bs[lk + 2][lr] = rb.z; Bs[lk + 3][lr] = rb.w;
        __syncthreads();

        if (kk + GK < D) {
            ra = *(const float4*)(Ap + kk + GK);
            rb = *(const float4*)(Bp + kk + GK);
        }

#pragma unroll
        for (int k = 0; k < GK; k++) {
            float4 a0 = *(const float4*)&As[k][ty * 8];
            float4 a1 = *(const float4*)&As[k][ty * 8 + 4];
            float4 b0 = *(const float4*)&Bs[k][tx * 8];
            float4 b1 = *(const float4*)&Bs[k][tx * 8 + 4];
            float av[8] = {a0.x, a0.y, a0.z, a0.w, a1.x, a1.y, a1.z, a1.w};
            float bv[8] = {b0.x, b0.y, b0.z, b0.w, b1.x, b1.y, b1.z, b1.w};
#pragma unroll
            for (int m = 0; m < 8; m++)
#pragma unroll
                for (int n = 0; n < 8; n++)
                    acc[m][n] = fmaf(av[m], bv[n], acc[m][n]);
        }
        __syncthreads();
    }

    float bv[8];
#pragma unroll
    for (int n = 0; n < 8; n++) bv[n] = bias[i0 + tx * 8 + n];

#pragma unroll
    for (int m = 0; m < 8; m++) {
        size_t row = (size_t)(t0 + ty * 8 + m) * D + i0 + tx * 8;
        float4 o0 = make_float4(acc[m][0] + bv[0], acc[m][1] + bv[1],
                                acc[m][2] + bv[2], acc[m][3] + bv[3]);
        float4 o1 = make_float4(acc[m][4] + bv[4], acc[m][5] + bv[5],
                                acc[m][6] + bv[6], acc[m][7] + bv[7]);
        *(float4*)&g_cp[row]     = o0;
        *(float4*)&g_cp[row + 4] = o1;
    }
}

// ============================================================
// Recurrence v2: 128 CTAs x 512 threads.
// Thread: c = tid & 127 (16 state cols c*16..c*16+15),
//         rgrp = tid >> 7 (4 rows: i0 + rgrp*4 .. +3).
// W slice (4 rows x 16 cols) in registers as f32x2 pairs.
// State read directly from `out` row t-1 via __ldcg (no smem staging).
// Per-producer spin: flag[c] is a monotonic step counter.
// Reduction: warp shuffle -> 512B double-buffered smem -> 16 finalize lanes.
// ============================================================
__global__ __launch_bounds__(REC_THREADS, 1) void recurrence_kernel(
    const float* __restrict__ W,
    float* out)
{
    __shared__ float s_red[2][16 * 4];   // [buf][row*4 + colpart]

    int tid  = threadIdx.x;
    int lane = tid & 31;
    int wrp  = tid >> 5;          // 0..15
    int c    = tid & 127;         // column segment (producer CTA index)
    int rgrp = tid >> 7;          // 0..3
    int wq   = wrp & 3;           // colpart within reduction
    int cta  = blockIdx.x;
    int i0   = cta * ROWS_PER_CTA;

    // ---- preload W slice as f32x2 pairs: w2[m][j] covers cols c*16+2j, +2j+1
    ull w2[4][8];
#pragma unroll
    for (int m = 0; m < 4; m++) {
        const float* wp = W + (size_t)(i0 + rgrp * 4 + m) * WSTRIDE + c * 16;
#pragma unroll
        for (int j = 0; j < 4; j++) {
            uint4 q = *(const uint4*)(wp + j * 4);
            w2[m][j * 2 + 0] = pack2(q.x, q.y);
            w2[m][j * 2 + 1] = pack2(q.z, q.w);
        }
    }

    const ull minus1 = pack2(__float_as_uint(-1.0f), __float_as_uint(-1.0f));

    for (int t = 0; t < S; t++) {
        // prefetch hc/cp for finalize lanes (independent of state; in flight
        // during spin + compute)
        float hcv = 0.0f, cpv = 0.0f;
        if (tid < ROWS_PER_CTA) {
            hcv = __ldg(&g_hc[(size_t)t * D + i0 + tid]);
            cpv = __ldg(&g_cp[(size_t)t * D + i0 + tid]);
        }

        // ---- obtain state segment ----
        ull sp[8];
        if (t == 0) {
#pragma unroll
            for (int j = 0; j < 8; j++) sp[j] = minus1;
        } else {
            // spin until this lane's producer has published row t-1
            // (lane polls its own flag; coalesced 1 line per warp)
            for (;;) {
                int f = *(volatile int*)&g_flag[c];
                if (__all_sync(0xFFFFFFFFu, f >= t)) break;
            }
            __threadfence();   // acquire: order state loads after flag read
            const float* src = out + (size_t)(t - 1) * D + c * 16;
#pragma unroll
            for (int j = 0; j < 4; j++) {
                uint4 q = __ldcg((const uint4*)(src + j * 4));
                sp[j * 2 + 0] = pack2(q.x, q.y);
                sp[j * 2 + 1] = pack2(q.z, q.w);
            }
        }

        // ---- 4-row x 16-col partial matvec, packed f32x2 ----
        ull a0 = 0, a1 = 0, a2 = 0, a3 = 0;
#pragma unroll
        for (int j = 0; j < 8; j++) {
            a0 = ffma2(w2[0][j], sp[j], a0);
            a1 = ffma2(w2[1][j], sp[j], a1);
            a2 = ffma2(w2[2][j], sp[j], a2);
            a3 = ffma2(w2[3][j], sp[j], a3);
        }
        float2 f0 = unpack2(a0), f1 = unpack2(a1),
               f2 = unpack2(a2), f3 = unpack2(a3);
        float r0 = f0.x + f0.y;
        float r1 = f1.x + f1.y;
        float r2 = f2.x + f2.y;
        float r3 = f3.x + f3.y;

        // ---- warp shuffle reduction over 32 column segments ----
#pragma unroll
        for (int off = 16; off > 0; off >>= 1) {
            r0 += __shfl_xor_sync(0xFFFFFFFFu, r0, off);
            r1 += __shfl_xor_sync(0xFFFFFFFFu, r1, off);
            r2 += __shfl_xor_sync(0xFFFFFFFFu, r2, off);
            r3 += __shfl_xor_sync(0xFFFFFFFFu, r3, off);
        }
        int buf = t & 1;
        if (lane == 0) {
            int rb = rgrp * 4;
            s_red[buf][(rb + 0) * 4 + wq] = r0;
            s_red[buf][(rb + 1) * 4 + wq] = r1;
            s_red[buf][(rb + 2) * 4 + wq] = r2;
            s_red[buf][(rb + 3) * 4 + wq] = r3;
        }
        __syncthreads();

        // ---- finalize: 16 lanes of warp 0 ----
        if (tid < ROWS_PER_CTA) {
            float s = s_red[buf][tid * 4 + 0] + s_red[buf][tid * 4 + 1]
                    + s_red[buf][tid * 4 + 2] + s_red[buf][tid * 4 + 3];
            float x  = s + cpv;
            float g  = 1.0f / (1.0f + __expf(-x));
            float ns = hcv * g;
            out[(size_t)t * D + i0 + tid] = ns;
            if (t == S - 1) out[(size_t)S * D + i0 + tid] = ns;  // final_state
            __threadfence();                  // each storing lane releases
            __syncwarp(0x0000FFFFu);
            if (tid == 0)
                *(volatile int*)&g_flag[cta] = t + 1;   // publish step t
        }
        // no second barrier: s_red is double-buffered, and buffer reuse at
        // t+2 is transitively gated by this CTA's own flag via the chain
        // (our flag t+1 -> others' step t+1 -> their flag t+2 -> our spin).
    }
}

// ============================================================
extern "C" void kernel_launch(void* const* d_in, const int* in_sizes, int n_in,
                              void* d_out, int out_size) {
    const float* ce = (const float*)d_in[0];   // (S, D)
    const float* W  = (const float*)d_in[1];   // (D, 2D)
    const float* b  = (const float*)d_in[2];   // (D,)
    float* out = (float*)d_out;                // (S*D + D) floats

    zero_flags_kernel<<<1, 128>>>();

    dim3 cgrid(D / 256, NCHUNK);
    cummax_chunk_kernel<<<cgrid, 256>>>(ce);
    cummax_scan_kernel<<<D / 256, 256>>>();
    cummax_write_kernel<<<cgrid, 256>>>(ce);

    dim3 ggrid(D / GI, S / GT);
    gemm_ctx_kernel<<<ggrid, 256>>>(ce, W, b);

    recurrence_kernel<<<NCTA_REC, REC_THREADS>>>(W, out);
}

// round 4
// speedup vs baseline: 2.8536x; 2.8536x over previous
#include <cuda_runtime.h>
#include <math.h>

#define S 8192
#define D 2048
#define WSTRIDE 4096           // W row stride (2*D)
#define NCTA_REC 128
#define ROWS_PER_CTA 16        // D / NCTA_REC
#define NCHUNK 64
#define CHUNK 128              // S / NCHUNK
#define REC_THREADS 512

typedef unsigned long long ull;

// ---- scratch (no runtime allocation allowed) ----
__device__ float g_hc[(size_t)S * D];        // cummax result
__device__ float g_cp[(size_t)S * D];        // ctx_proj result
__device__ float g_chunkmax[NCHUNK * D];     // cummax phase-B scratch
__device__ int   g_cnt[S];                   // per-step completion counter (0..128)

#define NEG_INF __int_as_float(0xff800000)

// ---- packed f32x2 helpers ----
__device__ __forceinline__ ull ffma2(ull a, ull b, ull c) {
    ull d;
    asm("fma.rn.f32x2 %0, %1, %2, %3;" : "=l"(d) : "l"(a), "l"(b), "l"(c));
    return d;
}
__device__ __forceinline__ ull pack2(unsigned int lo, unsigned int hi) {
    ull v;
    asm("mov.b64 %0, {%1, %2};" : "=l"(v) : "r"(lo), "r"(hi));
    return v;
}
__device__ __forceinline__ ull pack2f(float x, float y) {
    ull v;
    asm("mov.b64 %0, {%1, %2};" : "=l"(v) : "f"(x), "f"(y));
    return v;
}
__device__ __forceinline__ ull dup2f(float x) {
    ull v;
    asm("mov.b64 %0, {%1, %1};" : "=l"(v) : "f"(x));
    return v;
}
__device__ __forceinline__ float2 unpack2(ull v) {
    float2 r;
    asm("mov.b64 {%0, %1}, %2;" : "=f"(r.x), "=f"(r.y) : "l"(v));
    return r;
}

// ---- fence-free acquire/release primitives ----
__device__ __forceinline__ int ld_acquire_gpu(const int* p) {
    int v;
    asm volatile("ld.acquire.gpu.global.s32 %0, [%1];" : "=r"(v) : "l"(p) : "memory");
    return v;
}
__device__ __forceinline__ void red_release_gpu_add(int* p, int v) {
    asm volatile("red.release.gpu.global.add.s32 [%0], %1;" :: "l"(p), "r"(v) : "memory");
}

// ============================================================
// counter reset (graph replays must start from zeroed counters)
// ============================================================
__global__ void zero_flags_kernel() {
    int idx = blockIdx.x * blockDim.x + threadIdx.x;
    if (idx < S) g_cnt[idx] = 0;
}

// ============================================================
// cummax phase A: per-(chunk, col) max
// ============================================================
__global__ void cummax_chunk_kernel(const float* __restrict__ ce) {
    int col = blockIdx.x * blockDim.x + threadIdx.x;
    int chunk = blockIdx.y;
    const float* p = ce + (size_t)chunk * CHUNK * D + col;
    float m = NEG_INF;
#pragma unroll 8
    for (int r = 0; r < CHUNK; r++) {
        m = fmaxf(m, p[(size_t)r * D]);
    }
    g_chunkmax[chunk * D + col] = m;
}

// ============================================================
// cummax phase B: exclusive prefix-max over chunks, per column
// ============================================================
__global__ void cummax_scan_kernel() {
    int col = blockIdx.x * blockDim.x + threadIdx.x;
    float run = NEG_INF;
    for (int ch = 0; ch < NCHUNK; ch++) {
        float v = g_chunkmax[ch * D + col];
        g_chunkmax[ch * D + col] = run;   // exclusive prefix
        run = fmaxf(run, v);
    }
}

// ============================================================
// cummax phase C: inclusive scan within chunk seeded by prefix
// ============================================================
__global__ void cummax_write_kernel(const float* __restrict__ ce) {
    int col = blockIdx.x * blockDim.x + threadIdx.x;
    int chunk = blockIdx.y;
    float m = g_chunkmax[chunk * D + col];
    const float* p = ce + (size_t)chunk * CHUNK * D + col;
    float*       q = g_hc + (size_t)chunk * CHUNK * D + col;
#pragma unroll 8
    for (int r = 0; r < CHUNK; r++) {
        m = fmaxf(m, p[(size_t)r * D]);
        q[(size_t)r * D] = m;
    }
}

// ============================================================
// GEMM: g_cp[t][i] = sum_j ce[t][j] * W[i][D + j] + b[i]
// f32x2 packed FFMA: accumulators are (n, n+1) pairs.
// ============================================================
#define GT 128
#define GI 128
#define GK 8
#define GPAD 4

__global__ __launch_bounds__(256) void gemm_ctx_kernel(
    const float* __restrict__ A,
    const float* __restrict__ W,
    const float* __restrict__ bias)
{
    __shared__ float As[GK][GT + GPAD];
    __shared__ float Bs[GK][GI + GPAD];

    int tid = threadIdx.x;
    int tx = tid & 15;
    int ty = tid >> 4;
    int i0 = blockIdx.x * GI;
    int t0 = blockIdx.y * GT;

    int lr = tid >> 1;
    int lk = (tid & 1) * 4;

    const float* Ap = A + (size_t)(t0 + lr) * D + lk;
    const float* Bp = W + (size_t)(i0 + lr) * WSTRIDE + D + lk;

    ull acc[8][4];
#pragma unroll
    for (int m = 0; m < 8; m++)
#pragma unroll
        for (int n = 0; n < 4; n++) acc[m][n] = 0ULL;

    float4 ra = *(const float4*)Ap;
    float4 rb = *(const float4*)Bp;

    for (int kk = 0; kk < D; kk += GK) {
        As[lk + 0][lr] = ra.x; As[lk + 1][lr] = ra.y;
        As[lk + 2][lr] = ra.z; As[lk + 3][lr] = ra.w;
        Bs[lk + 0][lr] = rb.x; Bs[lk + 1][lr] = rb.y;
        Bs[lk + 2][lr] = rb.z; Bs[lk + 3][lr] = rb.w;
        __syncthreads();

        if (kk + GK < D) {
            ra = *(const float4*)(Ap + kk + GK);
            rb = *(const float4*)(Bp + kk + GK);
        }

#pragma unroll
        for (int k = 0; k < GK; k++) {
            float4 a0 = *(const float4*)&As[k][ty * 8];
            float4 a1 = *(const float4*)&As[k][ty * 8 + 4];
            float4 b0 = *(const float4*)&Bs[k][tx * 8];
            float4 b1 = *(const float4*)&Bs[k][tx * 8 + 4];
            ull bp[4] = {pack2f(b0.x, b0.y), pack2f(b0.z, b0.w),
                         pack2f(b1.x, b1.y), pack2f(b1.z, b1.w)};
            ull ad[8] = {dup2f(a0.x), dup2f(a0.y), dup2f(a0.z), dup2f(a0.w),
                         dup2f(a1.x), dup2f(a1.y), dup2f(a1.z), dup2f(a1.w)};
#pragma unroll
            for (int m = 0; m < 8; m++)
#pragma unroll
                for (int n = 0; n < 4; n++)
                    acc[m][n] = ffma2(ad[m], bp[n], acc[m][n]);
        }
        __syncthreads();
    }

    float bv[8];
#pragma unroll
    for (int n = 0; n < 8; n++) bv[n] = bias[i0 + tx * 8 + n];

#pragma unroll
    for (int m = 0; m < 8; m++) {
        size_t row = (size_t)(t0 + ty * 8 + m) * D + i0 + tx * 8;
        float2 c0 = unpack2(acc[m][0]), c1 = unpack2(acc[m][1]);
        float2 c2 = unpack2(acc[m][2]), c3 = unpack2(acc[m][3]);
        float4 o0 = make_float4(c0.x + bv[0], c0.y + bv[1],
                                c1.x + bv[2], c1.y + bv[3]);
        float4 o1 = make_float4(c2.x + bv[4], c2.y + bv[5],
                                c3.x + bv[6], c3.y + bv[7]);
        *(float4*)&g_cp[row]     = o0;
        *(float4*)&g_cp[row + 4] = o1;
    }
}

// ============================================================
// Recurrence v3: 128 CTAs x 512 threads, fence-free acquire/release sync.
// Thread: c = tid & 127 (16 state cols c*16..+15), rgrp = tid >> 7 (4 rows).
// W slice in registers (f32x2). State via __ldcg from `out` row t-1.
// Sync: producers red.release.gpu add g_cnt[t]; tid 0 polls g_cnt[t-1]
// with ld.acquire.gpu, then __syncthreads releases the CTA.
// ============================================================
__global__ __launch_bounds__(REC_THREADS, 1) void recurrence_kernel(
    const float* __restrict__ W,
    float* out)
{
    __shared__ float s_red[2][16 * 4];   // [buf][row*4 + colpart]

    int tid  = threadIdx.x;
    int lane = tid & 31;
    int wrp  = tid >> 5;          // 0..15
    int c    = tid & 127;         // column segment
    int rgrp = tid >> 7;          // 0..3
    int wq   = wrp & 3;           // colpart within reduction
    int cta  = blockIdx.x;
    int i0   = cta * ROWS_PER_CTA;

    // ---- preload W slice as f32x2 pairs ----
    ull w2[4][8];
#pragma unroll
    for (int m = 0; m < 4; m++) {
        const float* wp = W + (size_t)(i0 + rgrp * 4 + m) * WSTRIDE + c * 16;
#pragma unroll
        for (int j = 0; j < 4; j++) {
            uint4 q = *(const uint4*)(wp + j * 4);
            w2[m][j * 2 + 0] = pack2(q.x, q.y);
            w2[m][j * 2 + 1] = pack2(q.z, q.w);
        }
    }

    const ull minus1 = pack2(__float_as_uint(-1.0f), __float_as_uint(-1.0f));

    for (int t = 0; t < S; t++) {
        // prefetch hc/cp for finalize lanes (in flight during spin)
        float hcv = 0.0f, cpv = 0.0f;
        if (tid < ROWS_PER_CTA) {
            hcv = __ldg(&g_hc[(size_t)t * D + i0 + tid]);
            cpv = __ldg(&g_cp[(size_t)t * D + i0 + tid]);
        }

        // ---- wait for row t-1 to be fully published ----
        if (t > 0 && tid == 0) {
            while (ld_acquire_gpu(&g_cnt[t - 1]) < NCTA_REC) { }
        }
        __syncthreads();   // propagates tid0's acquire to the whole CTA

        // ---- obtain state segment (L2-direct; never cached in L1) ----
        ull sp[8];
        if (t == 0) {
#pragma unroll
            for (int j = 0; j < 8; j++) sp[j] = minus1;
        } else {
            const float* src = out + (size_t)(t - 1) * D + c * 16;
#pragma unroll
            for (int j = 0; j < 4; j++) {
                uint4 q = __ldcg((const uint4*)(src + j * 4));
                sp[j * 2 + 0] = pack2(q.x, q.y);
                sp[j * 2 + 1] = pack2(q.z, q.w);
            }
        }

        // ---- 4-row x 16-col partial matvec, packed f32x2 ----
        ull a0 = 0, a1 = 0, a2 = 0, a3 = 0;
#pragma unroll
        for (int j = 0; j < 8; j++) {
            a0 = ffma2(w2[0][j], sp[j], a0);
            a1 = ffma2(w2[1][j], sp[j], a1);
            a2 = ffma2(w2[2][j], sp[j], a2);
            a3 = ffma2(w2[3][j], sp[j], a3);
        }
        float2 f0 = unpack2(a0), f1 = unpack2(a1),
               f2 = unpack2(a2), f3 = unpack2(a3);
        float r0 = f0.x + f0.y;
        float r1 = f1.x + f1.y;
        float r2 = f2.x + f2.y;
        float r3 = f3.x + f3.y;

        // ---- warp shuffle reduction over 32 column segments ----
#pragma unroll
        for (int off = 16; off > 0; off >>= 1) {
            r0 += __shfl_xor_sync(0xFFFFFFFFu, r0, off);
            r1 += __shfl_xor_sync(0xFFFFFFFFu, r1, off);
            r2 += __shfl_xor_sync(0xFFFFFFFFu, r2, off);
            r3 += __shfl_xor_sync(0xFFFFFFFFu, r3, off);
        }
        int buf = t & 1;
        if (lane == 0) {
            int rb = rgrp * 4;
            s_red[buf][(rb + 0) * 4 + wq] = r0;
            s_red[buf][(rb + 1) * 4 + wq] = r1;
            s_red[buf][(rb + 2) * 4 + wq] = r2;
            s_red[buf][(rb + 3) * 4 + wq] = r3;
        }
        __syncthreads();

        // ---- finalize: 16 lanes of warp 0 ----
        if (tid < ROWS_PER_CTA) {
            float s = s_red[buf][tid * 4 + 0] + s_red[buf][tid * 4 + 1]
                    + s_red[buf][tid * 4 + 2] + s_red[buf][tid * 4 + 3];
            float x  = s + cpv;
            float g  = 1.0f / (1.0f + __expf(-x));
            float ns = hcv * g;
            __stcg(&out[(size_t)t * D + i0 + tid], ns);
            if (t == S - 1) __stcg(&out[(size_t)S * D + i0 + tid], ns);
            __syncwarp(0x0000FFFFu);   // all 16 stores done (orders them
                                       // before lane 0's release below)
            if (tid == 0)
                red_release_gpu_add(&g_cnt[t], 1);   // publish step t
        }
        // s_red reuse at t+1 is safe: writes at t+1 occur after the t+1
        // top-of-loop __syncthreads, which follows every reader's access.
    }
}

// ============================================================
extern "C" void kernel_launch(void* const* d_in, const int* in_sizes, int n_in,
                              void* d_out, int out_size) {
    const float* ce = (const float*)d_in[0];   // (S, D)
    const float* W  = (const float*)d_in[1];   // (D, 2D)
    const float* b  = (const float*)d_in[2];   // (D,)
    float* out = (float*)d_out;                // (S*D + D) floats

    zero_flags_kernel<<<(S + 1023) / 1024, 1024>>>();

    dim3 cgrid(D / 256, NCHUNK);
    cummax_chunk_kernel<<<cgrid, 256>>>(ce);
    cummax_scan_kernel<<<D / 256, 256>>>();
    cummax_write_kernel<<<cgrid, 256>>>(ce);

    dim3 ggrid(D / GI, S / GT);
    gemm_ctx_kernel<<<ggrid, 256>>>(ce, W, b);

    recurrence_kernel<<<NCTA_REC, REC_THREADS>>>(W, out);
}